// round 5
// baseline (speedup 1.0000x reference)
#include <cuda_runtime.h>
#include <math.h>

// DehLoss: O(n^2) pairwise Gaussian-kernel loss, n = 8192.
// R_i = g1_i + log(y_i), h = 1.3*n^-0.2, dr_ij = (R_i - R_j)/h
// Dk_j = sum_i d_i*phi(dr_ij);  LP_j = sum_i L_i*ndtr(dr_ij), L_i = exp(g2_i-g1_i)
// out = -(S1+S2+S3+S4)
//
// R5: R3's proven pair-loop shape (JT=128, unroll 8, single packed accumulator
// chain) + last-block-done fused epilogue (2 launches total) + pre-packed
// shared tiles loaded via ld.shared.v2.u64 (no per-body pack movs).

#define N      8192
#define SPLITS 16
#define CHUNK  (N / SPLITS)   // 512 columns per split
#define JT     128
#define GX     (N / JT)       // 64 j-blocks
#define TOTAL_BLOCKS (GX * SPLITS)

typedef unsigned long long u64;

__device__ float4 g_A[N / 2];     // {Rh_2m, Rh_2m+1, d_2m, d_2m+1}
__device__ float2 g_Lp[N / 2];    // {L_2m, L_2m+1}
__device__ float  g_rowRh[N];     // compacted Rh_j for rows with d_j=1
__device__ int    g_M;            // number of compacted rows
__device__ float  g_Lsum;         // sum of L over all i
__device__ int    g_ctr;          // last-block-done counter (reset in prep)
__device__ float  g_partDk[SPLITS * N];
__device__ float  g_partLP[SPLITS * N];

__device__ __forceinline__ float ex2f_(float x) {
    float r; asm("ex2.approx.ftz.f32 %0, %1;" : "=f"(r) : "f"(x)); return r;
}
__device__ __forceinline__ float rcpf_(float x) {
    float r; asm("rcp.approx.ftz.f32 %0, %1;" : "=f"(r) : "f"(x)); return r;
}
__device__ __forceinline__ u64 pk2(float lo, float hi) {
    u64 r; asm("mov.b64 %0, {%1, %2};" : "=l"(r) : "f"(lo), "f"(hi)); return r;
}
__device__ __forceinline__ void upk2(u64 v, float& lo, float& hi) {
    asm("mov.b64 {%0, %1}, %2;" : "=f"(lo), "=f"(hi) : "l"(v));
}
__device__ __forceinline__ u64 fma2_(u64 a, u64 b, u64 c) {
    u64 d; asm("fma.rn.f32x2 %0, %1, %2, %3;" : "=l"(d) : "l"(a), "l"(b), "l"(c)); return d;
}
__device__ __forceinline__ u64 mul2_(u64 a, u64 b) {
    u64 d; asm("mul.rn.f32x2 %0, %1, %2;" : "=l"(d) : "l"(a), "l"(b)); return d;
}
__device__ __forceinline__ u64 add2_(u64 a, u64 b) {
    u64 d; asm("add.rn.f32x2 %0, %1, %2;" : "=l"(d) : "l"(a), "l"(b)); return d;
}

// Fused: per-i preprocessing + Lsum + deterministic compaction of d_j==1 rows.
__global__ void __launch_bounds__(1024) prep_kernel(const float* __restrict__ mz,
                                                    const float* __restrict__ y,
                                                    const float* __restrict__ delta,
                                                    float inv_h) {
    __shared__ int    cnt[1024];
    __shared__ double lred[1024];
    const int t = threadIdx.x;
    const int base = t * 8;
    if (t == 0) g_ctr = 0;

    float Rh[8]; int flags[8]; int c = 0; double ls = 0.0;
    #pragma unroll
    for (int q = 0; q < 8; ++q) {
        int j = base + q;
        float g1 = mz[2 * j], g2 = mz[2 * j + 1];
        float R = g1 + logf(y[j]);
        Rh[q] = R * inv_h;
        float d = delta[j];
        float L = expf(g2 - g1);
        ls += (double)L;
        flags[q] = d > 0.5f;
        c += flags[q];
        if (q & 1) {
            float4 a; a.x = Rh[q - 1]; a.y = Rh[q];
            a.z = (float)flags[q - 1]; a.w = (float)flags[q];
            g_A[j >> 1] = a;
            float g2p = mz[2 * (j - 1) + 1], g1p = mz[2 * (j - 1)];
            g_Lp[j >> 1] = make_float2(expf(g2p - g1p), L);
        }
    }
    cnt[t] = c; lred[t] = ls;
    __syncthreads();
    for (int off = 1; off < 1024; off <<= 1) {
        int v = (t >= off) ? cnt[t - off] : 0;
        __syncthreads();
        cnt[t] += v;
        __syncthreads();
    }
    int pos = cnt[t] - c;
    #pragma unroll
    for (int q = 0; q < 8; ++q) {
        if (flags[q]) g_rowRh[pos++] = Rh[q];
    }
    if (t == 1023) g_M = cnt[1023];
    for (int s = 512; s > 0; s >>= 1) {
        if (t < s) lred[t] += lred[t + s];
        __syncthreads();
    }
    if (t == 0) g_Lsum = (float)lred[0];
}

__global__ void __launch_bounds__(JT) pair_kernel(const float* __restrict__ mz,
                                                  float h, float* __restrict__ out) {
    __shared__ uint4  shA[CHUNK / 2];   // {Rh2 (u64), d2 (u64)} pre-packed
    __shared__ float2 shL[CHUNK / 2];
    __shared__ double red[JT];
    __shared__ int    lastFlag;

    const int tid = threadIdx.x;
    const int M = g_M;
    const bool active = (int)(blockIdx.x * JT) < M;

    if (active) {
        const int c  = blockIdx.x * JT + tid;
        const int cc = min(c, M - 1);
        const int base2 = blockIdx.y * (CHUNK / 2);

        for (int k = tid; k < CHUNK / 2; k += JT) {
            shA[k] = ((const uint4*)g_A)[base2 + k];
            shL[k] = g_Lp[base2 + k];
        }
        const float Rhj = g_rowRh[cc];
        __syncthreads();

        const unsigned sA = (unsigned)__cvta_generic_to_shared(shA);
        const unsigned sL = (unsigned)__cvta_generic_to_shared(shL);

        // C1 = -0.5*log2(e), C2 = log2(1/sqrt(2*pi)); AS 26.2.16 coeffs negated.
        const u64 nRhj2 = pk2(-Rhj, -Rhj);
        const u64 C1_2  = pk2(-0.72134752044448170f, -0.72134752044448170f);
        const u64 C2_2  = pk2(-1.32574806473615923f, -1.32574806473615923f);
        const u64 PP2   = pk2(0.33267f, 0.33267f);
        const u64 ONE2  = pk2(1.0f, 1.0f);
        const u64 HALF2 = pk2(0.5f, 0.5f);
        const u64 NA1_2 = pk2(-0.4361836f, -0.4361836f);
        const u64 NA2_2 = pk2( 0.1201676f,  0.1201676f);
        const u64 NA3_2 = pk2(-0.9372980f, -0.9372980f);
        const u64 AMSK  = 0x7FFFFFFF7FFFFFFFULL;
        const u64 SMSK  = 0x8000000080000000ULL;

        u64 dk2 = 0ULL, lp2 = 0ULL;

        #pragma unroll 8
        for (int k = 0; k < CHUNK / 2; ++k) {
            u64 Rh2, d2, L2;
            asm("ld.shared.v2.u64 {%0, %1}, [%2];"
                : "=l"(Rh2), "=l"(d2) : "r"(sA + k * 16));
            asm("ld.shared.u64 %0, [%1];"
                : "=l"(L2) : "r"(sL + k * 8));

            u64 dr2 = add2_(Rh2, nRhj2);               // (R_i - R_j)/h, 2 lanes
            u64 e2  = fma2_(mul2_(dr2, C1_2), dr2, C2_2);
            float elo, ehi; upk2(e2, elo, ehi);
            u64 phi2 = pk2(ex2f_(elo), ex2f_(ehi));    // normal pdf, both lanes
            dk2 = fma2_(d2, phi2, dk2);

            u64 den2 = fma2_(dr2 & AMSK, PP2, ONE2);   // 1 + p|dr|
            float dlo, dhi; upk2(den2, dlo, dhi);
            float rr = rcpf_(dlo * dhi);               // one rcp, both lanes
            u64 t2 = pk2(rr * dhi, rr * dlo);          // {1/dlo, 1/dhi}

            u64 p2 = fma2_(t2, NA3_2, NA2_2);          // -poly3(t), Horner
            p2 = fma2_(t2, p2, NA1_2);
            p2 = mul2_(t2, p2);
            u64 u2 = fma2_(phi2, p2, HALF2);           // 0.5 - q >= 0
            lp2 = fma2_(L2, u2 | (dr2 & SMSK), lp2);   // ndtr(dr) - 0.5
        }

        float dka, dkb, lpa, lpb;
        upk2(dk2, dka, dkb);
        upk2(lp2, lpa, lpb);
        if (c < M) {
            g_partDk[blockIdx.y * N + c] = dka + dkb;
            g_partLP[blockIdx.y * N + c] = lpa + lpb;
        }
    }

    // ---- last-block-done: the final arriving block reduces everything ----
    __threadfence();
    if (tid == 0) {
        int prev = atomicAdd(&g_ctr, 1);
        lastFlag = (prev == TOTAL_BLOCKS - 1);
    }
    __syncthreads();
    if (!lastFlag) return;

    const float Lsum   = g_Lsum;
    const float inv_nh = 1.0f / ((float)N * h);
    const float invn   = 1.0f / (float)N;
    double acc = 0.0;

    // S1 + S2: d_j * (g2_j - R_j) over all j
    for (int j = tid; j < N; j += JT) {
        float4 a = g_A[j >> 1];
        float Rh = (j & 1) ? a.y : a.x;
        float d  = (j & 1) ? a.w : a.z;
        float g2 = mz[2 * j + 1];
        acc += (double)(d * (g2 - Rh * h));
    }
    // S3 + S4 over compacted rows
    for (int c = tid; c < M; c += JT) {
        float dk = 0.0f, lp = 0.0f;
        #pragma unroll
        for (int s2 = 0; s2 < SPLITS; ++s2) {
            dk += g_partDk[s2 * N + c];
            lp += g_partLP[s2 * N + c];
        }
        float Dk = dk * inv_nh;
        float LP = (lp + 0.5f * Lsum) * invn;
        acc += (double)(logf(Dk + 1e-15f) - logf(LP + 1e-15f));
    }
    red[tid] = acc;
    __syncthreads();
    for (int s = JT / 2; s > 0; s >>= 1) {
        if (tid < s) red[tid] += red[tid + s];
        __syncthreads();
    }
    if (tid == 0) out[0] = (float)(-red[0] / (double)N);
}

extern "C" void kernel_launch(void* const* d_in, const int* in_sizes, int n_in,
                              void* d_out, int out_size) {
    const float* mz    = (const float*)d_in[0];
    const float* y     = (const float*)d_in[1];
    const float* delta = (const float*)d_in[2];
    float* out = (float*)d_out;

    const double hd = 1.3 * pow((double)N, -0.2);

    prep_kernel<<<1, 1024>>>(mz, y, delta, (float)(1.0 / hd));
    dim3 grid(GX, SPLITS);
    pair_kernel<<<grid, JT>>>(mz, (float)hd, out);
}

// round 6
// speedup vs baseline: 2.0018x; 2.0018x over previous
#include <cuda_runtime.h>
#include <math.h>

// DehLoss: O(n^2) pairwise Gaussian-kernel loss, n = 8192.
// R_i = g1_i + log(y_i), h = 1.3*n^-0.2, dr_ij = (R_i - R_j)/h
// Dk_j = sum_i d_i*phi(dr_ij);  LP_j = sum_i L_i*ndtr(dr_ij), L_i = exp(g2_i-g1_i)
// out = -(S1+S2+S3+S4)
//
// R6: pair kernel restored to the proven R3 shape (JT=128, unroll 8, single
// packed f32x2 accumulators, C++ shared loads). Changes vs R3:
//  - SPLITS 16 -> 32 (2x resident warps; the loop is dependency-stall-bound)
//  - out_kernel merged into reduce_kernel (last-block-done among 32 blocks)
// 3 launches total.

#define N      8192
#define SPLITS 32
#define CHUNK  (N / SPLITS)   // 256 columns per split
#define JT     128
#define GX     (N / JT)       // 64 j-blocks
#define RB     32             // reduce blocks

typedef unsigned long long u64;

__device__ float4 g_A[N / 2];     // {Rh_2m, Rh_2m+1, d_2m, d_2m+1}
__device__ float2 g_Lp[N / 2];    // {L_2m, L_2m+1}
__device__ float  g_rowRh[N];     // compacted Rh_j for rows with d_j=1
__device__ int    g_M;            // number of compacted rows
__device__ float  g_Lsum;         // sum of L over all i
__device__ int    g_ctr;          // last-block counter for reduce (reset in prep)
__device__ float  g_partDk[SPLITS * N];
__device__ float  g_partLP[SPLITS * N];
__device__ double g_bsum[RB];

__device__ __forceinline__ float ex2f_(float x) {
    float r; asm("ex2.approx.ftz.f32 %0, %1;" : "=f"(r) : "f"(x)); return r;
}
__device__ __forceinline__ float rcpf_(float x) {
    float r; asm("rcp.approx.ftz.f32 %0, %1;" : "=f"(r) : "f"(x)); return r;
}
__device__ __forceinline__ u64 pk2(float lo, float hi) {
    u64 r; asm("mov.b64 %0, {%1, %2};" : "=l"(r) : "f"(lo), "f"(hi)); return r;
}
__device__ __forceinline__ void upk2(u64 v, float& lo, float& hi) {
    asm("mov.b64 {%0, %1}, %2;" : "=f"(lo), "=f"(hi) : "l"(v));
}
__device__ __forceinline__ u64 fma2_(u64 a, u64 b, u64 c) {
    u64 d; asm("fma.rn.f32x2 %0, %1, %2, %3;" : "=l"(d) : "l"(a), "l"(b), "l"(c)); return d;
}
__device__ __forceinline__ u64 mul2_(u64 a, u64 b) {
    u64 d; asm("mul.rn.f32x2 %0, %1, %2;" : "=l"(d) : "l"(a), "l"(b)); return d;
}
__device__ __forceinline__ u64 add2_(u64 a, u64 b) {
    u64 d; asm("add.rn.f32x2 %0, %1, %2;" : "=l"(d) : "l"(a), "l"(b)); return d;
}

// Fused: per-i preprocessing + Lsum + deterministic compaction of d_j==1 rows.
__global__ void __launch_bounds__(1024) prep_kernel(const float* __restrict__ mz,
                                                    const float* __restrict__ y,
                                                    const float* __restrict__ delta,
                                                    float inv_h) {
    __shared__ int    cnt[1024];
    __shared__ double lred[1024];
    const int t = threadIdx.x;
    const int base = t * 8;
    if (t == 0) g_ctr = 0;

    float Rh[8]; int flags[8]; int c = 0; double ls = 0.0;
    #pragma unroll
    for (int q = 0; q < 8; ++q) {
        int j = base + q;
        float g1 = mz[2 * j], g2 = mz[2 * j + 1];
        float R = g1 + logf(y[j]);
        Rh[q] = R * inv_h;
        float d = delta[j];
        float L = expf(g2 - g1);
        ls += (double)L;
        flags[q] = d > 0.5f;
        c += flags[q];
        if (q & 1) {
            float4 a; a.x = Rh[q - 1]; a.y = Rh[q];
            a.z = (float)flags[q - 1]; a.w = (float)flags[q];
            g_A[j >> 1] = a;
            float g2p = mz[2 * (j - 1) + 1], g1p = mz[2 * (j - 1)];
            g_Lp[j >> 1] = make_float2(expf(g2p - g1p), L);
        }
    }
    cnt[t] = c; lred[t] = ls;
    __syncthreads();
    for (int off = 1; off < 1024; off <<= 1) {
        int v = (t >= off) ? cnt[t - off] : 0;
        __syncthreads();
        cnt[t] += v;
        __syncthreads();
    }
    int pos = cnt[t] - c;
    #pragma unroll
    for (int q = 0; q < 8; ++q) {
        if (flags[q]) g_rowRh[pos++] = Rh[q];
    }
    if (t == 1023) g_M = cnt[1023];
    for (int s = 512; s > 0; s >>= 1) {
        if (t < s) lred[t] += lred[t + s];
        __syncthreads();
    }
    if (t == 0) g_Lsum = (float)lred[0];
}

__global__ void __launch_bounds__(JT) pair_kernel() {
    __shared__ float4 shA[CHUNK / 2];
    __shared__ float2 shL[CHUNK / 2];
    const int M = g_M;
    if ((int)(blockIdx.x * JT) >= M) return;

    const int c  = blockIdx.x * JT + threadIdx.x;
    const int cc = min(c, M - 1);
    const int base2 = blockIdx.y * (CHUNK / 2);

    for (int k = threadIdx.x; k < CHUNK / 2; k += JT) {
        shA[k] = g_A[base2 + k];
        shL[k] = g_Lp[base2 + k];
    }
    const float Rhj = g_rowRh[cc];
    __syncthreads();

    // C1 = -0.5*log2(e), C2 = log2(1/sqrt(2*pi)); AS 26.2.16: p=0.33267,
    // a1=0.4361836, a2=-0.1201676, a3=0.9372980 (negated for the 0.5 - q fma).
    const u64 nRhj2 = pk2(-Rhj, -Rhj);
    const u64 C1_2  = pk2(-0.72134752044448170f, -0.72134752044448170f);
    const u64 C2_2  = pk2(-1.32574806473615923f, -1.32574806473615923f);
    const u64 PP2   = pk2(0.33267f, 0.33267f);
    const u64 ONE2  = pk2(1.0f, 1.0f);
    const u64 HALF2 = pk2(0.5f, 0.5f);
    const u64 NA1_2 = pk2(-0.4361836f, -0.4361836f);
    const u64 NA2_2 = pk2( 0.1201676f,  0.1201676f);
    const u64 NA3_2 = pk2(-0.9372980f, -0.9372980f);
    const u64 AMSK  = 0x7FFFFFFF7FFFFFFFULL;
    const u64 SMSK  = 0x8000000080000000ULL;

    u64 dk2 = 0ULL, lp2 = 0ULL;

    #pragma unroll 8
    for (int k = 0; k < CHUNK / 2; ++k) {
        float4 a = shA[k];
        float2 L = shL[k];
        u64 Rh2 = pk2(a.x, a.y);
        u64 d2  = pk2(a.z, a.w);
        u64 L2  = pk2(L.x, L.y);

        u64 dr2 = add2_(Rh2, nRhj2);               // (R_i - R_j)/h, 2 lanes
        u64 e2  = fma2_(mul2_(dr2, C1_2), dr2, C2_2);
        float elo, ehi; upk2(e2, elo, ehi);
        u64 phi2 = pk2(ex2f_(elo), ex2f_(ehi));    // normal pdf, both lanes
        dk2 = fma2_(d2, phi2, dk2);

        u64 den2 = fma2_(dr2 & AMSK, PP2, ONE2);   // 1 + p|dr|
        float dlo, dhi; upk2(den2, dlo, dhi);
        float rr = rcpf_(dlo * dhi);               // one rcp, both lanes
        u64 t2 = pk2(rr * dhi, rr * dlo);          // {1/dlo, 1/dhi}

        u64 p2 = fma2_(t2, NA3_2, NA2_2);          // -poly3(t), Horner
        p2 = fma2_(t2, p2, NA1_2);
        p2 = mul2_(t2, p2);
        u64 u2 = fma2_(phi2, p2, HALF2);           // 0.5 - q >= 0
        u64 v2 = u2 | (dr2 & SMSK);                // ndtr(dr) - 0.5
        lp2 = fma2_(L2, v2, lp2);
    }

    float dka, dkb, lpa, lpb;
    upk2(dk2, dka, dkb);
    upk2(lp2, lpa, lpb);
    if (c < M) {
        g_partDk[blockIdx.y * N + c] = dka + dkb;
        g_partLP[blockIdx.y * N + c] = lpa + lpb;
    }
}

// Parallel epilogue: one column (and one j of S1+S2) per thread, 32 blocks.
// Final 32-value sum done by the last-arriving block (fixed-order shfl tree
// over a fixed array -> deterministic).
__global__ void __launch_bounds__(256) reduce_kernel(const float* __restrict__ mz,
                                                     float h, float* __restrict__ out) {
    __shared__ double red[256];
    __shared__ int    lastFlag;
    const int t   = threadIdx.x;
    const int gid = blockIdx.x * 256 + t;    // 0 .. 8191
    const int M   = g_M;
    const float Lsum   = g_Lsum;
    const float inv_nh = 1.0f / ((float)N * h);
    const float invn   = 1.0f / (float)N;

    double acc = 0.0;

    // S1 + S2: d_j * (g2_j - R_j)
    {
        float4 a = g_A[gid >> 1];
        float Rh = (gid & 1) ? a.y : a.x;
        float d  = (gid & 1) ? a.w : a.z;
        float g2 = mz[2 * gid + 1];
        acc += (double)(d * (g2 - Rh * h));
    }
    // S3 + S4 over compacted rows
    if (gid < M) {
        float dk = 0.0f, lp = 0.0f;
        #pragma unroll
        for (int s2 = 0; s2 < SPLITS; ++s2) {
            dk += g_partDk[s2 * N + gid];
            lp += g_partLP[s2 * N + gid];
        }
        float Dk = dk * inv_nh;
        float LP = (lp + 0.5f * Lsum) * invn;
        acc += (double)(logf(Dk + 1e-15f) - logf(LP + 1e-15f));
    }
    red[t] = acc;
    __syncthreads();
    for (int s = 128; s > 0; s >>= 1) {
        if (t < s) red[t] += red[t + s];
        __syncthreads();
    }
    if (t == 0) g_bsum[blockIdx.x] = red[0];

    __threadfence();
    if (t == 0) {
        int prev = atomicAdd(&g_ctr, 1);
        lastFlag = (prev == RB - 1);
    }
    __syncthreads();
    if (!lastFlag) return;

    if (t < 32) {
        double v = g_bsum[t];
        #pragma unroll
        for (int s = 16; s > 0; s >>= 1)
            v += __shfl_down_sync(0xFFFFFFFFu, v, s);
        if (t == 0) out[0] = (float)(-v / (double)N);
    }
}

extern "C" void kernel_launch(void* const* d_in, const int* in_sizes, int n_in,
                              void* d_out, int out_size) {
    const float* mz    = (const float*)d_in[0];
    const float* y     = (const float*)d_in[1];
    const float* delta = (const float*)d_in[2];
    float* out = (float*)d_out;

    const double hd = 1.3 * pow((double)N, -0.2);

    prep_kernel<<<1, 1024>>>(mz, y, delta, (float)(1.0 / hd));
    dim3 grid(GX, SPLITS);
    pair_kernel<<<grid, JT>>>();
    reduce_kernel<<<RB, 256>>>(mz, (float)hd, out);
}

// round 7
// speedup vs baseline: 2.2602x; 1.1291x over previous
#include <cuda_runtime.h>
#include <math.h>

// DehLoss: O(n^2) pairwise Gaussian-kernel loss, n = 8192.
// R_i = g1_i + log(y_i), h = 1.3*n^-0.2, dr_ij = (R_i - R_j)/h
// Dk_j = sum_i d_i*phi(dr_ij);  LP_j = sum_i L_i*ndtr(dr_ij), L_i = exp(g2_i-g1_i)
// out = -(S1+S2+S3+S4)
//
// R7: prep parallelized to 32 blocks (was 1 block / 18us). Compaction offsets
// computed with NO inter-block communication: each block redundantly counts
// delta flags below its segment (L2-cached), local offset via ballot+prefix.
// Lsum computed block-redundantly in reduce (fixed order -> deterministic).
// Pair kernel: unchanged from R6 (proven shape). 3 launches.

#define N      8192
#define SPLITS 32
#define CHUNK  (N / SPLITS)   // 256 columns per split
#define JT     128
#define GX     (N / JT)       // 64 j-blocks
#define RB     32             // reduce blocks
#define PB     32             // prep blocks
#define PT     256            // prep threads

typedef unsigned long long u64;

__device__ float4 g_A[N / 2];     // {Rh_2m, Rh_2m+1, d_2m, d_2m+1}
__device__ float2 g_Lp[N / 2];    // {L_2m, L_2m+1}
__device__ float  g_rowRh[N];     // compacted Rh_j for rows with d_j=1
__device__ int    g_M;            // number of compacted rows
__device__ int    g_ctr;          // last-block counter for reduce (reset in prep)
__device__ float  g_partDk[SPLITS * N];
__device__ float  g_partLP[SPLITS * N];
__device__ double g_bsum[RB];

__device__ __forceinline__ float ex2f_(float x) {
    float r; asm("ex2.approx.ftz.f32 %0, %1;" : "=f"(r) : "f"(x)); return r;
}
__device__ __forceinline__ float rcpf_(float x) {
    float r; asm("rcp.approx.ftz.f32 %0, %1;" : "=f"(r) : "f"(x)); return r;
}
__device__ __forceinline__ u64 pk2(float lo, float hi) {
    u64 r; asm("mov.b64 %0, {%1, %2};" : "=l"(r) : "f"(lo), "f"(hi)); return r;
}
__device__ __forceinline__ void upk2(u64 v, float& lo, float& hi) {
    asm("mov.b64 {%0, %1}, %2;" : "=f"(lo), "=f"(hi) : "l"(v));
}
__device__ __forceinline__ u64 fma2_(u64 a, u64 b, u64 c) {
    u64 d; asm("fma.rn.f32x2 %0, %1, %2, %3;" : "=l"(d) : "l"(a), "l"(b), "l"(c)); return d;
}
__device__ __forceinline__ u64 mul2_(u64 a, u64 b) {
    u64 d; asm("mul.rn.f32x2 %0, %1, %2;" : "=l"(d) : "l"(a), "l"(b)); return d;
}
__device__ __forceinline__ u64 add2_(u64 a, u64 b) {
    u64 d; asm("add.rn.f32x2 %0, %1, %2;" : "=l"(d) : "l"(a), "l"(b)); return d;
}

// 32 blocks x 256 threads, one row per thread. No inter-block communication.
__global__ void __launch_bounds__(PT) prep_kernel(const float* __restrict__ mz,
                                                  const float* __restrict__ y,
                                                  const float* __restrict__ delta,
                                                  float inv_h) {
    __shared__ int sred[PT];
    __shared__ int wcnt[PT / 32];
    const int b = blockIdx.x;
    const int t = threadIdx.x;
    const int j = b * PT + t;

    if (b == 0 && t == 0) g_ctr = 0;   // reset last-block counter each replay

    float g1 = mz[2 * j], g2 = mz[2 * j + 1];
    float Rh = (g1 + logf(y[j])) * inv_h;
    float L  = expf(g2 - g1);
    int  flag = delta[j] > 0.5f;

    // pack pairs via shfl (lane+1 is the odd row of the pair)
    float Rh_hi = __shfl_down_sync(0xFFFFFFFFu, Rh, 1);
    float L_hi  = __shfl_down_sync(0xFFFFFFFFu, L, 1);
    int   f_hi  = __shfl_down_sync(0xFFFFFFFFu, flag, 1);
    if ((t & 1) == 0) {
        float4 a; a.x = Rh; a.y = Rh_hi; a.z = (float)flag; a.w = (float)f_hi;
        g_A[j >> 1] = a;
        g_Lp[j >> 1] = make_float2(L, L_hi);
    }

    // global base for this block: count flags in delta[0 .. b*PT) (redundant,
    // coalesced, L2-resident; deterministic).
    int base = 0;
    for (int k = t; k < b * PT; k += PT) base += (delta[k] > 0.5f);
    sred[t] = base;
    __syncthreads();
    #pragma unroll
    for (int s = PT / 2; s > 0; s >>= 1) {
        if (t < s) sred[t] += sred[t + s];
        __syncthreads();
    }
    const int blockBase = sred[0];

    // local offset: warp ballot + cross-warp prefix
    const int lane = t & 31, w = t >> 5;
    unsigned bal = __ballot_sync(0xFFFFFFFFu, flag);
    int lpref  = __popc(bal & ((1u << lane) - 1u));
    if (lane == 0) wcnt[w] = __popc(bal);
    __syncthreads();
    int woff = 0;
    #pragma unroll
    for (int q = 0; q < PT / 32; ++q) woff += (q < w) ? wcnt[q] : 0;

    if (flag) g_rowRh[blockBase + woff + lpref] = Rh;

    if (b == PB - 1 && t == 0) {
        int own = 0;
        #pragma unroll
        for (int q = 0; q < PT / 32; ++q) own += wcnt[q];
        g_M = blockBase + own;
    }
}

__global__ void __launch_bounds__(JT) pair_kernel() {
    __shared__ float4 shA[CHUNK / 2];
    __shared__ float2 shL[CHUNK / 2];
    const int M = g_M;
    if ((int)(blockIdx.x * JT) >= M) return;

    const int c  = blockIdx.x * JT + threadIdx.x;
    const int cc = min(c, M - 1);
    const int base2 = blockIdx.y * (CHUNK / 2);

    for (int k = threadIdx.x; k < CHUNK / 2; k += JT) {
        shA[k] = g_A[base2 + k];
        shL[k] = g_Lp[base2 + k];
    }
    const float Rhj = g_rowRh[cc];
    __syncthreads();

    // C1 = -0.5*log2(e), C2 = log2(1/sqrt(2*pi)); AS 26.2.16: p=0.33267,
    // a1=0.4361836, a2=-0.1201676, a3=0.9372980 (negated for the 0.5 - q fma).
    const u64 nRhj2 = pk2(-Rhj, -Rhj);
    const u64 C1_2  = pk2(-0.72134752044448170f, -0.72134752044448170f);
    const u64 C2_2  = pk2(-1.32574806473615923f, -1.32574806473615923f);
    const u64 PP2   = pk2(0.33267f, 0.33267f);
    const u64 ONE2  = pk2(1.0f, 1.0f);
    const u64 HALF2 = pk2(0.5f, 0.5f);
    const u64 NA1_2 = pk2(-0.4361836f, -0.4361836f);
    const u64 NA2_2 = pk2( 0.1201676f,  0.1201676f);
    const u64 NA3_2 = pk2(-0.9372980f, -0.9372980f);
    const u64 AMSK  = 0x7FFFFFFF7FFFFFFFULL;
    const u64 SMSK  = 0x8000000080000000ULL;

    u64 dk2 = 0ULL, lp2 = 0ULL;

    #pragma unroll 8
    for (int k = 0; k < CHUNK / 2; ++k) {
        float4 a = shA[k];
        float2 L = shL[k];
        u64 Rh2 = pk2(a.x, a.y);
        u64 d2  = pk2(a.z, a.w);
        u64 L2  = pk2(L.x, L.y);

        u64 dr2 = add2_(Rh2, nRhj2);               // (R_i - R_j)/h, 2 lanes
        u64 e2  = fma2_(mul2_(dr2, C1_2), dr2, C2_2);
        float elo, ehi; upk2(e2, elo, ehi);
        u64 phi2 = pk2(ex2f_(elo), ex2f_(ehi));    // normal pdf, both lanes
        dk2 = fma2_(d2, phi2, dk2);

        u64 den2 = fma2_(dr2 & AMSK, PP2, ONE2);   // 1 + p|dr|
        float dlo, dhi; upk2(den2, dlo, dhi);
        float rr = rcpf_(dlo * dhi);               // one rcp, both lanes
        u64 t2 = pk2(rr * dhi, rr * dlo);          // {1/dlo, 1/dhi}

        u64 p2 = fma2_(t2, NA3_2, NA2_2);          // -poly3(t), Horner
        p2 = fma2_(t2, p2, NA1_2);
        p2 = mul2_(t2, p2);
        u64 u2 = fma2_(phi2, p2, HALF2);           // 0.5 - q >= 0
        u64 v2 = u2 | (dr2 & SMSK);                // ndtr(dr) - 0.5
        lp2 = fma2_(L2, v2, lp2);
    }

    float dka, dkb, lpa, lpb;
    upk2(dk2, dka, dkb);
    upk2(lp2, lpa, lpb);
    if (c < M) {
        g_partDk[blockIdx.y * N + c] = dka + dkb;
        g_partLP[blockIdx.y * N + c] = lpa + lpb;
    }
}

// Parallel epilogue: one column (and one j of S1+S2) per thread, 32 blocks.
// Lsum computed block-redundantly (identical fixed order in every block).
// Final 32-value sum by last-arriving block (fixed-order shfl -> deterministic).
__global__ void __launch_bounds__(256) reduce_kernel(const float* __restrict__ mz,
                                                     float h, float* __restrict__ out) {
    __shared__ double red[256];
    __shared__ int    lastFlag;
    const int t   = threadIdx.x;
    const int gid = blockIdx.x * 256 + t;    // 0 .. 8191
    const int M   = g_M;
    const float inv_nh = 1.0f / ((float)N * h);
    const float invn   = 1.0f / (float)N;

    // block-redundant Lsum (same order in every block -> same value)
    double ls = 0.0;
    for (int m = t; m < N / 2; m += 256) {
        float2 L = g_Lp[m];
        ls += (double)L.x + (double)L.y;
    }
    red[t] = ls;
    __syncthreads();
    for (int s = 128; s > 0; s >>= 1) {
        if (t < s) red[t] += red[t + s];
        __syncthreads();
    }
    const float Lsum = (float)red[0];
    __syncthreads();

    double acc = 0.0;
    // S1 + S2: d_j * (g2_j - R_j)
    {
        float4 a = g_A[gid >> 1];
        float Rh = (gid & 1) ? a.y : a.x;
        float d  = (gid & 1) ? a.w : a.z;
        float g2 = mz[2 * gid + 1];
        acc += (double)(d * (g2 - Rh * h));
    }
    // S3 + S4 over compacted rows
    if (gid < M) {
        float dk = 0.0f, lp = 0.0f;
        #pragma unroll
        for (int s2 = 0; s2 < SPLITS; ++s2) {
            dk += g_partDk[s2 * N + gid];
            lp += g_partLP[s2 * N + gid];
        }
        float Dk = dk * inv_nh;
        float LP = (lp + 0.5f * Lsum) * invn;
        acc += (double)(logf(Dk + 1e-15f) - logf(LP + 1e-15f));
    }
    red[t] = acc;
    __syncthreads();
    for (int s = 128; s > 0; s >>= 1) {
        if (t < s) red[t] += red[t + s];
        __syncthreads();
    }
    if (t == 0) g_bsum[blockIdx.x] = red[0];

    __threadfence();
    if (t == 0) {
        int prev = atomicAdd(&g_ctr, 1);
        lastFlag = (prev == RB - 1);
    }
    __syncthreads();
    if (!lastFlag) return;

    if (t < 32) {
        double v = g_bsum[t];
        #pragma unroll
        for (int s = 16; s > 0; s >>= 1)
            v += __shfl_down_sync(0xFFFFFFFFu, v, s);
        if (t == 0) out[0] = (float)(-v / (double)N);
    }
}

extern "C" void kernel_launch(void* const* d_in, const int* in_sizes, int n_in,
                              void* d_out, int out_size) {
    const float* mz    = (const float*)d_in[0];
    const float* y     = (const float*)d_in[1];
    const float* delta = (const float*)d_in[2];
    float* out = (float*)d_out;

    const double hd = 1.3 * pow((double)N, -0.2);

    prep_kernel<<<PB, PT>>>(mz, y, delta, (float)(1.0 / hd));
    dim3 grid(GX, SPLITS);
    pair_kernel<<<grid, JT>>>();
    reduce_kernel<<<RB, 256>>>(mz, (float)hd, out);
}